// round 11
// baseline (speedup 1.0000x reference)
#include <cuda_runtime.h>

#define HH   256
#define WWD  256
#define PIX  (HH * WWD)
#define NCH  29
#define NB   2
#define NTAP 49
#define SPLANE 1008   // 14 * 72
#define SSTR   72

// Persistent scratch (allocation-free rule: __device__ globals).
__device__ __align__(128) float g_W[NB * NTAP * PIX];   // combined per-pixel 7x7 weights
__device__ __align__(128) float g_q[NB * NCH * PIX];    // current q (in-place update)
__device__ __align__(128) float g_P[NB * NCH * PIX];    // pairwise scratch

// ---------------------------------------------------------------------------
// Kernel 1: W[k,p] = sw[k] * (3 + 10*exp(-||I(p+k)-I(p)||^2 / 200)), 0 if OOB
// One launch per batch (keeps pairwise at ncu capture slot -s 5).
// ---------------------------------------------------------------------------
__global__ void compute_w_kernel(const float* __restrict__ img, int b) {
    int p = blockIdx.x * blockDim.x + threadIdx.x;
    int y = p >> 8, x = p & 255;
    const float* im = img + (size_t)b * 3 * PIX;
    float r0 = im[p], gg0 = im[PIX + p], bb0 = im[2 * PIX + p];

    // normalized 1D gaussian (sigma=3, size 7)
    float g1[7]; float s = 0.f;
    #pragma unroll
    for (int i = 0; i < 7; i++) {
        float d = (float)i - 3.0f;
        g1[i] = __expf(-d * d * (1.0f / 18.0f));
        s += g1[i];
    }
    float inv = __fdividef(1.0f, s);
    #pragma unroll
    for (int i = 0; i < 7; i++) g1[i] *= inv;

    float* wp = g_W + (size_t)b * NTAP * PIX;
    #pragma unroll
    for (int dy = 0; dy < 7; dy++) {
        int ny = y + dy - 3;
        #pragma unroll
        for (int dx = 0; dx < 7; dx++) {
            int nx = x + dx - 3;
            float wv = 0.f;
            if (ny >= 0 && ny < HH && nx >= 0 && nx < WWD) {
                int np = ny * WWD + nx;
                float dr = im[np] - r0;
                float dg = im[PIX + np] - gg0;
                float db = im[2 * PIX + np] - bb0;
                float d2 = dr * dr + dg * dg + db * db;
                wv = g1[dy] * g1[dx] * (3.0f + 10.0f * __expf(-d2 * 0.005f));
            }
            wp[(dy * 7 + dx) * PIX + p] = wv;
        }
    }
}

// ---------------------------------------------------------------------------
// Kernel 2: softmax over channels, SCALAR (1 pixel/thread, ~50 regs).
// use_p=0: logits=-unary (init). use_p=1: logits=P-unary. Writes qdst (or g_q).
// ---------------------------------------------------------------------------
__global__ __launch_bounds__(256) void softmax_kernel(
    const float* __restrict__ unary, int use_p, float* __restrict__ qdst)
{
    int p = blockIdx.x * blockDim.x + threadIdx.x;  // pixel index
    int b = blockIdx.y;
    const float* ub = unary + (size_t)b * NCH * PIX + p;
    const float* pb = g_P + (size_t)b * NCH * PIX + p;
    float* qb = (qdst ? qdst : g_q) + (size_t)b * NCH * PIX + p;

    float l[NCH];
    float m = -1e30f;
    if (use_p) {
        #pragma unroll
        for (int c = 0; c < NCH; c++) {
            l[c] = __ldg(pb + c * PIX) - __ldg(ub + c * PIX);
            m = fmaxf(m, l[c]);
        }
    } else {
        #pragma unroll
        for (int c = 0; c < NCH; c++) {
            l[c] = -__ldg(ub + c * PIX);
            m = fmaxf(m, l[c]);
        }
    }
    float s = 0.f;
    #pragma unroll
    for (int c = 0; c < NCH; c++) { l[c] = __expf(l[c] - m); s += l[c]; }
    float r = __fdividef(1.f, s);
    #pragma unroll
    for (int c = 0; c < NCH; c++) qb[c * PIX] = l[c] * r;
}

// ---------------------------------------------------------------------------
// Kernel 3: pairwise conv: P[c,p] = sum_k W[k,p]*q[c,p+k]
// CTA = 64x8 spatial tile x 8-channel group. 128 threads, 4 px/thread.
// W rows double-buffered across dy to hide L2 latency.
// ---------------------------------------------------------------------------
template<int NC>
__device__ __forceinline__ void conv_group(
    const float* __restrict__ qin_b, float* __restrict__ Pb, int c0,
    float* __restrict__ qs,
    const int (&goffs)[8], unsigned lmask, unsigned smask,
    int tid, int px, int py, const float* __restrict__ wbase, int gp)
{
    // cooperative fill of NC channel tiles (with zero halo)
    #pragma unroll
    for (int cc = 0; cc < NC; cc++) {
        const float* src = qin_b + (c0 + cc) * PIX;
        #pragma unroll
        for (int j = 0; j < 8; j++) {
            if (smask & (1u << j)) {
                float v = (lmask & (1u << j)) ? __ldg(src + goffs[j]) : 0.f;
                qs[cc * SPLANE + tid + j * 128] = v;
            }
        }
    }
    __syncthreads();

    float z[NC][4];
    #pragma unroll
    for (int cc = 0; cc < NC; cc++) { z[cc][0] = 0.f; z[cc][1] = 0.f; z[cc][2] = 0.f; z[cc][3] = 0.f; }

    // preload W row dy=0
    float4 w4[7], w4n[7];
    #pragma unroll
    for (int dx = 0; dx < 7; dx++)
        w4[dx] = __ldg((const float4*)(wbase + dx * PIX));

    #pragma unroll 1
    for (int dy = 0; dy < 7; dy++) {
        // prefetch next dy's W row (redundant reload of row 6 on last iter)
        const float* wnext = wbase + (dy < 6 ? dy + 1 : 6) * 7 * PIX;
        #pragma unroll
        for (int dx = 0; dx < 7; dx++)
            w4n[dx] = __ldg((const float4*)(wnext + dx * PIX));

        #pragma unroll
        for (int cc = 0; cc < NC; cc++) {
            const float* qr = qs + cc * SPLANE + (py + dy) * SSTR + px;
            float4 qa = *(const float4*)qr;
            float4 qb4 = *(const float4*)(qr + 4);
            float2 qc = *(const float2*)(qr + 8);
            float qv[10] = {qa.x, qa.y, qa.z, qa.w, qb4.x, qb4.y, qb4.z, qb4.w, qc.x, qc.y};
            #pragma unroll
            for (int dx = 0; dx < 7; dx++) {
                z[cc][0] = fmaf(w4[dx].x, qv[dx + 0], z[cc][0]);
                z[cc][1] = fmaf(w4[dx].y, qv[dx + 1], z[cc][1]);
                z[cc][2] = fmaf(w4[dx].z, qv[dx + 2], z[cc][2]);
                z[cc][3] = fmaf(w4[dx].w, qv[dx + 3], z[cc][3]);
            }
        }
        #pragma unroll
        for (int dx = 0; dx < 7; dx++) w4[dx] = w4n[dx];
    }

    #pragma unroll
    for (int cc = 0; cc < NC; cc++)
        *(float4*)(Pb + (size_t)(c0 + cc) * PIX + gp) =
            make_float4(z[cc][0], z[cc][1], z[cc][2], z[cc][3]);
}

__global__ __launch_bounds__(128, 4) void pairwise_kernel() {
    __shared__ float qs[8 * SPLANE];   // 31.5 KB
    int tx = threadIdx.x, ty = threadIdx.y;        // 16 x 8
    int tid = ty * 16 + tx;
    int x0 = blockIdx.x * 64, y0 = blockIdx.y * 8;
    int zb = blockIdx.z;                            // 0..4*NB-1
    int b = zb >> 2, grp = zb & 3;

    const float* qin_b = g_q + (size_t)b * NCH * PIX;
    float* Pb = g_P + (size_t)b * NCH * PIX;
    const float* wbase = g_W + (size_t)b * NTAP * PIX + (y0 + ty) * WWD + x0 + tx * 4;

    // halo-fill addressing: 1008 smem slots / 128 threads -> 8 each
    int goffs[8]; unsigned lmask = 0, smask = 0;
    #pragma unroll
    for (int j = 0; j < 8; j++) {
        int idx = tid + j * 128;
        int row = idx / SSTR;
        int col = idx - row * SSTR;
        int gy = y0 - 3 + row, gx = x0 - 3 + col;
        bool instore = idx < SPLANE;
        bool v = instore && (col < 70) && gy >= 0 && gy < HH && gx >= 0 && gx < WWD;
        goffs[j] = v ? gy * WWD + gx : 0;
        if (instore) smask |= 1u << j;
        if (v)       lmask |= 1u << j;
    }

    int px = tx * 4, py = ty;
    int gp = (y0 + py) * WWD + x0 + px;

    if (grp < 3)
        conv_group<8>(qin_b, Pb, grp * 8, qs, goffs, lmask, smask, tid, px, py, wbase, gp);
    else
        conv_group<5>(qin_b, Pb, 24, qs, goffs, lmask, smask, tid, px, py, wbase, gp);
}

// ---------------------------------------------------------------------------
extern "C" void kernel_launch(void* const* d_in, const int* in_sizes, int n_in,
                              void* d_out, int out_size) {
    (void)in_sizes; (void)n_in; (void)out_size;
    const float* unary = (const float*)d_in[0];
    const float* img   = (const float*)d_in[1];
    float* out = (float*)d_out;

    // launches: 0:W(b0) 1:W(b1) 2:sm_init 3:pw 4:sm 5:pw <- ncu -s 5 captures pairwise
    compute_w_kernel<<<PIX / 256, 256>>>(img, 0);
    compute_w_kernel<<<PIX / 256, 256>>>(img, 1);
    softmax_kernel<<<dim3(PIX / 256, NB), 256>>>(unary, 0, nullptr);   // init q

    dim3 pgrid(WWD / 64, HH / 8, 4 * NB), pblk(16, 8);
    for (int it = 0; it < 5; it++) {
        pairwise_kernel<<<pgrid, pblk>>>();
        softmax_kernel<<<dim3(PIX / 256, NB), 256>>>(unary, 1, (it == 4) ? out : nullptr);
    }
}

// round 17
// speedup vs baseline: 1.1739x; 1.1739x over previous
#include <cuda_runtime.h>

#define HH   256
#define WWD  256
#define PIX  (HH * WWD)
#define NCH  29
#define NB   2
#define NTAP 49
#define SPLANE 1008   // 14 * 72
#define SSTR   72

// Persistent scratch (allocation-free rule: __device__ globals).
__device__ __align__(128) float g_W[NB * NTAP * PIX];   // combined per-pixel 7x7 weights
__device__ __align__(128) float g_q[NB * NCH * PIX];    // current q (in-place update)
__device__ __align__(128) float g_P[NB * NCH * PIX];    // pairwise scratch

// ---------------------------------------------------------------------------
// Kernel 1: W[k,p] = sw[k] * (3 + 10*exp(-||I(p+k)-I(p)||^2 / 200)), 0 if OOB
// ---------------------------------------------------------------------------
__global__ void compute_w_kernel(const float* __restrict__ img, int b) {
    int p = blockIdx.x * blockDim.x + threadIdx.x;
    int y = p >> 8, x = p & 255;
    const float* im = img + (size_t)b * 3 * PIX;
    float r0 = im[p], gg0 = im[PIX + p], bb0 = im[2 * PIX + p];

    // normalized 1D gaussian (sigma=3, size 7)
    float g1[7]; float s = 0.f;
    #pragma unroll
    for (int i = 0; i < 7; i++) {
        float d = (float)i - 3.0f;
        g1[i] = __expf(-d * d * (1.0f / 18.0f));
        s += g1[i];
    }
    float inv = __fdividef(1.0f, s);
    #pragma unroll
    for (int i = 0; i < 7; i++) g1[i] *= inv;

    float* wp = g_W + (size_t)b * NTAP * PIX;
    #pragma unroll
    for (int dy = 0; dy < 7; dy++) {
        int ny = y + dy - 3;
        #pragma unroll
        for (int dx = 0; dx < 7; dx++) {
            int nx = x + dx - 3;
            float wv = 0.f;
            if (ny >= 0 && ny < HH && nx >= 0 && nx < WWD) {
                int np = ny * WWD + nx;
                float dr = im[np] - r0;
                float dg = im[PIX + np] - gg0;
                float db = im[2 * PIX + np] - bb0;
                float d2 = dr * dr + dg * dg + db * db;
                wv = g1[dy] * g1[dx] * (3.0f + 10.0f * __expf(-d2 * 0.005f));
            }
            wp[(dy * 7 + dx) * PIX + p] = wv;
        }
    }
}

// ---------------------------------------------------------------------------
// Kernel 2: softmax over channels, scalar (1 pixel/thread).
// use_p=0: logits=-unary (init). use_p=1: logits=P-unary. Writes qdst (or g_q).
// ---------------------------------------------------------------------------
__global__ __launch_bounds__(256) void softmax_kernel(
    const float* __restrict__ unary, int use_p, float* __restrict__ qdst)
{
    int p = blockIdx.x * blockDim.x + threadIdx.x;  // pixel index
    int b = blockIdx.y;
    const float* ub = unary + (size_t)b * NCH * PIX + p;
    const float* pb = g_P + (size_t)b * NCH * PIX + p;
    float* qb = (qdst ? qdst : g_q) + (size_t)b * NCH * PIX + p;

    float l[NCH];
    float m = -1e30f;
    if (use_p) {
        #pragma unroll
        for (int c = 0; c < NCH; c++) {
            l[c] = __ldg(pb + c * PIX) - __ldg(ub + c * PIX);
            m = fmaxf(m, l[c]);
        }
    } else {
        #pragma unroll
        for (int c = 0; c < NCH; c++) {
            l[c] = -__ldg(ub + c * PIX);
            m = fmaxf(m, l[c]);
        }
    }
    float s = 0.f;
    #pragma unroll
    for (int c = 0; c < NCH; c++) { l[c] = __expf(l[c] - m); s += l[c]; }
    float r = __fdividef(1.f, s);
    #pragma unroll
    for (int c = 0; c < NCH; c++) qb[c * PIX] = l[c] * r;
}

// ---------------------------------------------------------------------------
// Kernel 3: pairwise conv: P[c,p] = sum_k W[k,p]*q[c,p+k]
// CTA = 64x8 spatial tile x 5-channel group (6 groups: 5,5,5,5,5,4).
// 128 threads, 4 px/thread. Lean regs -> 6 CTAs/SM = 24 warps.
// ---------------------------------------------------------------------------
#define NCG 5   // channels per group (last group has 4)

template<int NC>
__device__ __forceinline__ void conv_group(
    const float* __restrict__ qin_b, float* __restrict__ Pb, int c0,
    float* __restrict__ qs,
    const int (&goffs)[8], unsigned lmask, unsigned smask,
    int tid, int px, int py, const float* __restrict__ wbase, int gp)
{
    // cooperative fill of NC channel tiles (with zero halo)
    #pragma unroll
    for (int cc = 0; cc < NC; cc++) {
        const float* src = qin_b + (c0 + cc) * PIX;
        #pragma unroll
        for (int j = 0; j < 8; j++) {
            if (smask & (1u << j)) {
                float v = (lmask & (1u << j)) ? __ldg(src + goffs[j]) : 0.f;
                qs[cc * SPLANE + tid + j * 128] = v;
            }
        }
    }
    __syncthreads();

    float z[NC][4];
    #pragma unroll
    for (int cc = 0; cc < NC; cc++) { z[cc][0] = 0.f; z[cc][1] = 0.f; z[cc][2] = 0.f; z[cc][3] = 0.f; }

    #pragma unroll 1
    for (int dy = 0; dy < 7; dy++) {
        float4 w4[7];
        const float* wrow = wbase + dy * 7 * PIX;
        #pragma unroll
        for (int dx = 0; dx < 7; dx++)
            w4[dx] = __ldg((const float4*)(wrow + dx * PIX));
        #pragma unroll
        for (int cc = 0; cc < NC; cc++) {
            const float* qr = qs + cc * SPLANE + (py + dy) * SSTR + px;
            float4 qa = *(const float4*)qr;
            float4 qb4 = *(const float4*)(qr + 4);
            float2 qc = *(const float2*)(qr + 8);
            float qv[10] = {qa.x, qa.y, qa.z, qa.w, qb4.x, qb4.y, qb4.z, qb4.w, qc.x, qc.y};
            #pragma unroll
            for (int dx = 0; dx < 7; dx++) {
                z[cc][0] = fmaf(w4[dx].x, qv[dx + 0], z[cc][0]);
                z[cc][1] = fmaf(w4[dx].y, qv[dx + 1], z[cc][1]);
                z[cc][2] = fmaf(w4[dx].z, qv[dx + 2], z[cc][2]);
                z[cc][3] = fmaf(w4[dx].w, qv[dx + 3], z[cc][3]);
            }
        }
    }

    #pragma unroll
    for (int cc = 0; cc < NC; cc++)
        *(float4*)(Pb + (size_t)(c0 + cc) * PIX + gp) =
            make_float4(z[cc][0], z[cc][1], z[cc][2], z[cc][3]);
}

__global__ __launch_bounds__(128, 6) void pairwise_kernel() {
    __shared__ float qs[NCG * SPLANE];   // 19.7 KB
    int tx = threadIdx.x, ty = threadIdx.y;        // 16 x 8
    int tid = ty * 16 + tx;
    int x0 = blockIdx.x * 64, y0 = blockIdx.y * 8;
    int zb = blockIdx.z;                            // 0..6*NB-1
    int b = zb / 6, grp = zb % 6;

    const float* qin_b = g_q + (size_t)b * NCH * PIX;
    float* Pb = g_P + (size_t)b * NCH * PIX;
    const float* wbase = g_W + (size_t)b * NTAP * PIX + (y0 + ty) * WWD + x0 + tx * 4;

    // halo-fill addressing: 1008 smem slots / 128 threads -> 8 each
    int goffs[8]; unsigned lmask = 0, smask = 0;
    #pragma unroll
    for (int j = 0; j < 8; j++) {
        int idx = tid + j * 128;
        int row = idx / SSTR;
        int col = idx - row * SSTR;
        int gy = y0 - 3 + row, gx = x0 - 3 + col;
        bool instore = idx < SPLANE;
        bool v = instore && (col < 70) && gy >= 0 && gy < HH && gx >= 0 && gx < WWD;
        goffs[j] = v ? gy * WWD + gx : 0;
        if (instore) smask |= 1u << j;
        if (v)       lmask |= 1u << j;
    }

    int px = tx * 4, py = ty;
    int gp = (y0 + py) * WWD + x0 + px;

    if (grp < 5)
        conv_group<5>(qin_b, Pb, grp * 5, qs, goffs, lmask, smask, tid, px, py, wbase, gp);
    else
        conv_group<4>(qin_b, Pb, 25, qs, goffs, lmask, smask, tid, px, py, wbase, gp);
}

// ---------------------------------------------------------------------------
extern "C" void kernel_launch(void* const* d_in, const int* in_sizes, int n_in,
                              void* d_out, int out_size) {
    (void)in_sizes; (void)n_in; (void)out_size;
    const float* unary = (const float*)d_in[0];
    const float* img   = (const float*)d_in[1];
    float* out = (float*)d_out;

    // launches: 0:W(b0) 1:W(b1) 2:sm_init 3:pw 4:sm 5:pw <- ncu -s 5 captures pairwise
    compute_w_kernel<<<PIX / 256, 256>>>(img, 0);
    compute_w_kernel<<<PIX / 256, 256>>>(img, 1);
    softmax_kernel<<<dim3(PIX / 256, NB), 256>>>(unary, 0, nullptr);   // init q

    dim3 pgrid(WWD / 64, HH / 8, 6 * NB), pblk(16, 8);
    for (int it = 0; it < 5; it++) {
        pairwise_kernel<<<pgrid, pblk>>>();
        softmax_kernel<<<dim3(PIX / 256, NB), 256>>>(unary, 1, (it == 4) ? out : nullptr);
    }
}